// round 3
// baseline (speedup 1.0000x reference)
#include <cuda_runtime.h>
#include <cstdint>
#include <cstddef>

// ---------------------------------------------------------------------------
// NonLocalMSA: x[16,64,256,256] -> (qkv 1x1 + dw3x3 fused) -> window MSA -> proj
// Windows 8x8 of 32x32, heads=8, head_dim = 4*32*64 = 8192.
// head h of a window owns window-rows 4h..4h+3 (head = b0_local/4).
//
// Head-dim ordering: reference flattens (b0r,b1,c); we use d -> (b0r,c,b1)
// consistently for q,k,v and the output scatter -> results identical (the
// contracted head dim is permutation invariant), gathers 128B-coalesced.
// ---------------------------------------------------------------------------

#define HW      65536
#define BATCH   16
#define CIN     64
#define C3      192
#define HEADS   8

__device__ float g_qkv2  [BATCH * C3 * HW];                 // dw output (805MB)
__device__ float g_attout[BATCH * CIN * HW];                // attn out  (268MB)
__device__ float g_simp  [4 * BATCH * HEADS * 64 * 64];     // sim partials 8MB
__device__ float g_attnw [BATCH * HEADS * 64 * 64];         // softmax(attn) 2MB

// ---------------------------------------------------------------------------
// K1: fused 1x1 qkv GEMM + 3x3 depthwise.  Per block: 32x32 output tile,
// 34x34 halo, 16 output channels.  Pointwise accumulated in registers
// (acc[16][5]); dw staged through the (then-dead) Xs smem buffer in 2 passes.
// Grid: x = tile_x*12 + og  (og fastest -> L2 reuse of the x tile),
//       y = tile_y, z = batch.
// ---------------------------------------------------------------------------
__global__ __launch_bounds__(256) void k_qkvdw(const float* __restrict__ x,
                                               const float* __restrict__ wq,
                                               const float* __restrict__ wd)
{
    const int og    = blockIdx.x % 12;
    const int tx0   = (blockIdx.x / 12) * 32;
    const int ty0   = blockIdx.y * 32;
    const int b     = blockIdx.z;
    const int oBase = og * 16;

    __shared__ float buf[8 * 1160];     // Xs [c8][1156]  ->  Qs [o8][1156]
    __shared__ float Ws[16 * 64];
    __shared__ float Wd[16][9];

    const int t = threadIdx.x;

    // per-thread halo pixel slots (5 strided slots cover 1156 halo px)
    int  po[5]; bool pv[5];
    #pragma unroll
    for (int k = 0; k < 5; k++) {
        int idx = t + k * 256;
        int hy = idx / 34, hx = idx - hy * 34;
        int gy = ty0 - 1 + hy, gx = tx0 - 1 + hx;
        pv[k] = (idx < 1156) & (gy >= 0) & (gy < 256) & (gx >= 0) & (gx < 256);
        po[k] = (gy << 8) + gx;
    }

    #pragma unroll
    for (int i = 0; i < 4; i++)
        Ws[t + i * 256] = wq[oBase * 64 + t + i * 256];
    if (t < 144) Wd[t / 9][t % 9] = wd[(oBase + t / 9) * 9 + t % 9];

    float acc[16][5];
    #pragma unroll
    for (int o = 0; o < 16; o++)
        #pragma unroll
        for (int k = 0; k < 5; k++) acc[o][k] = 0.f;

    const float* xb = x + (size_t)b * CIN * HW;

    for (int cb = 0; cb < 64; cb += 8) {
        __syncthreads();
        #pragma unroll
        for (int c8 = 0; c8 < 8; c8++) {
            const float* in = xb + (size_t)(cb + c8) * HW;
            #pragma unroll
            for (int k = 0; k < 5; k++) {
                int idx = t + k * 256;
                if (idx < 1156) buf[c8 * 1160 + idx] = pv[k] ? in[po[k]] : 0.f;
            }
        }
        __syncthreads();
        #pragma unroll
        for (int c8 = 0; c8 < 8; c8++) {
            float xr[5];
            #pragma unroll
            for (int k = 0; k < 5; k++) {
                int idx = t + k * 256;
                xr[k] = (idx < 1156) ? buf[c8 * 1160 + idx] : 0.f;
            }
            #pragma unroll
            for (int o = 0; o < 16; o++) {
                float wv = Ws[o * 64 + cb + c8];
                #pragma unroll
                for (int k = 0; k < 5; k++) acc[o][k] += wv * xr[k];
            }
        }
    }

    // depthwise: 2 passes of 8 channels staged through buf
    const int col  = t & 31;
    const int row4 = (t >> 5) * 4;
    #pragma unroll
    for (int p = 0; p < 2; p++) {
        __syncthreads();
        #pragma unroll
        for (int o8 = 0; o8 < 8; o8++)
            #pragma unroll
            for (int k = 0; k < 5; k++) {
                int idx = t + k * 256;
                if (idx < 1156) buf[o8 * 1160 + idx] = acc[p * 8 + o8][k];
            }
        __syncthreads();
        #pragma unroll
        for (int o8 = 0; o8 < 8; o8++) {
            const int o = p * 8 + o8;
            const float* q = &buf[o8 * 1160];
            float s0 = 0.f, s1 = 0.f, s2 = 0.f, s3 = 0.f;
            #pragma unroll
            for (int hy = 0; hy < 6; hy++) {
                float v0 = q[(row4 + hy) * 34 + col];
                float v1 = q[(row4 + hy) * 34 + col + 1];
                float v2 = q[(row4 + hy) * 34 + col + 2];
                if (hy <= 2) { int dy = hy;
                    s0 += Wd[o][dy*3]*v0 + Wd[o][dy*3+1]*v1 + Wd[o][dy*3+2]*v2; }
                if (hy >= 1 && hy <= 3) { int dy = hy - 1;
                    s1 += Wd[o][dy*3]*v0 + Wd[o][dy*3+1]*v1 + Wd[o][dy*3+2]*v2; }
                if (hy >= 2 && hy <= 4) { int dy = hy - 2;
                    s2 += Wd[o][dy*3]*v0 + Wd[o][dy*3+1]*v1 + Wd[o][dy*3+2]*v2; }
                if (hy >= 3) { int dy = hy - 3;
                    s3 += Wd[o][dy*3]*v0 + Wd[o][dy*3+1]*v1 + Wd[o][dy*3+2]*v2; }
            }
            float* ob = g_qkv2 + (size_t)(b * C3 + oBase + o) * HW
                        + (size_t)(ty0 + row4) * 256 + tx0 + col;
            ob[0] = s0; ob[256] = s1; ob[512] = s2; ob[768] = s3;
        }
    }
}

// gather offset within a batch's 192*HW block (before qkv-channel offset)
__device__ __forceinline__ size_t qkv_off(int idx, int chunk, int h)
{
    int d    = idx & 63;
    int tok  = idx >> 6;
    int seg  = chunk * 2 + (d >> 5);
    int b0r  = seg >> 6;
    int c    = seg & 63;
    int row  = ((tok >> 3) << 5) + (h << 2) + b0r;
    int col  = ((tok & 7) << 5) + (d & 31);
    return ((size_t)c << 16) + (size_t)((row << 8) + col);
}

// ---------------------------------------------------------------------------
// K2: partial sim.  grid 512 = (bh)*4 parts, each accumulates 32 head-dim
// chunks into g_simp.  q/k staged transposed [d][tok] with float4-xor swizzle
// -> inner loop is 2x LDS.128 + 16 FFMA.
// Lane remap: warp tile = 32i x 16j (qr 128B 1-phase, kr 64B broadcast).
// ---------------------------------------------------------------------------
__global__ __launch_bounds__(256) void k_simp()
{
    const int blk  = blockIdx.x;
    const int part = blk & 3;
    const int bh   = blk >> 2;
    const int b    = bh >> 3;
    const int h    = bh & 7;

    __shared__ float qs[64 * 64];       // [d][swizzled tok-group]
    __shared__ float ks[64 * 64];

    const int t  = threadIdx.x;
    const int w  = t >> 5, l = t & 31;
    const int ti = (w & 1) * 8 + (l >> 2);   // i-group (4 i each)
    const int tj = (w >> 1) * 4 + (l & 3);   // j-group (4 j each)

    const float* src = g_qkv2 + (size_t)b * C3 * HW;

    float acc[4][4];
    #pragma unroll
    for (int i = 0; i < 4; i++)
        #pragma unroll
        for (int j = 0; j < 4; j++) acc[i][j] = 0.f;

    for (int cc = 0; cc < 32; cc++) {
        const int chunk = part * 32 + cc;
        __syncthreads();
        #pragma unroll
        for (int k = 0; k < 16; k++) {
            int idx = t + k * 256;
            int tok = idx >> 6, d = idx & 63;
            size_t off = qkv_off(idx, chunk, h);
            int gp = ((tok >> 2) ^ (d & 15)) & 15;
            int sc = d * 64 + gp * 4 + (tok & 3);
            qs[sc] = src[off];
            ks[sc] = src[((size_t)64 << 16) + off];
        }
        __syncthreads();
        #pragma unroll 4
        for (int dk = 0; dk < 64; dk++) {
            int m = dk & 15;
            float4 qr = *(const float4*)&qs[dk * 64 + ((ti ^ m) & 15) * 4];
            float4 kr = *(const float4*)&ks[dk * 64 + ((tj ^ m) & 15) * 4];
            acc[0][0] += qr.x * kr.x; acc[0][1] += qr.x * kr.y;
            acc[0][2] += qr.x * kr.z; acc[0][3] += qr.x * kr.w;
            acc[1][0] += qr.y * kr.x; acc[1][1] += qr.y * kr.y;
            acc[1][2] += qr.y * kr.z; acc[1][3] += qr.y * kr.w;
            acc[2][0] += qr.z * kr.x; acc[2][1] += qr.z * kr.y;
            acc[2][2] += qr.z * kr.z; acc[2][3] += qr.z * kr.w;
            acc[3][0] += qr.w * kr.x; acc[3][1] += qr.w * kr.y;
            acc[3][2] += qr.w * kr.z; acc[3][3] += qr.w * kr.w;
        }
    }

    float* dst = g_simp + ((size_t)part * (BATCH * HEADS) + bh) * 4096;
    #pragma unroll
    for (int ii = 0; ii < 4; ii++) {
        float4 v = make_float4(acc[ii][0], acc[ii][1], acc[ii][2], acc[ii][3]);
        *(float4*)&dst[(ti * 4 + ii) * 64 + tj * 4] = v;
    }
}

// ---------------------------------------------------------------------------
// K3: combine partials + scale + pos + softmax -> g_attnw.  grid 128 (tiny).
// ---------------------------------------------------------------------------
__global__ __launch_bounds__(256) void k_soft(const float* __restrict__ pos)
{
    const int bh = blockIdx.x;
    const int h  = bh & 7;
    const int t  = threadIdx.x;
    const int tj = t & 15;
    const int ti = t >> 4;
    const float scale = 0.011048543456039806f;   // 8192^-0.5

    #pragma unroll
    for (int ii = 0; ii < 4; ii++) {
        const int i = ti * 4 + ii;
        float s[4] = {0.f, 0.f, 0.f, 0.f};
        #pragma unroll
        for (int part = 0; part < 4; part++) {
            const float4 p4 = *(const float4*)&g_simp[
                ((size_t)part * (BATCH * HEADS) + bh) * 4096 + i * 64 + tj * 4];
            s[0] += p4.x; s[1] += p4.y; s[2] += p4.z; s[3] += p4.w;
        }
        const float4 pr = *(const float4*)&pos[((h * 64 + i) << 6) + tj * 4];
        s[0] = s[0] * scale + pr.x; s[1] = s[1] * scale + pr.y;
        s[2] = s[2] * scale + pr.z; s[3] = s[3] * scale + pr.w;

        float m = fmaxf(fmaxf(s[0], s[1]), fmaxf(s[2], s[3]));
        #pragma unroll
        for (int off = 1; off < 16; off <<= 1)
            m = fmaxf(m, __shfl_xor_sync(0xffffffffu, m, off));
        float e[4], sum = 0.f;
        #pragma unroll
        for (int jj = 0; jj < 4; jj++) { e[jj] = expf(s[jj] - m); sum += e[jj]; }
        #pragma unroll
        for (int off = 1; off < 16; off <<= 1)
            sum += __shfl_xor_sync(0xffffffffu, sum, off);
        float inv = 1.f / sum;
        float4 v4 = make_float4(e[0]*inv, e[1]*inv, e[2]*inv, e[3]*inv);
        *(float4*)&g_attnw[((size_t)bh * 64 + i) * 64 + tj * 4] = v4;
    }
}

// ---------------------------------------------------------------------------
// K4: out = attn @ v.  attn transposed in smem [j][i] so the inner loop is
// 2x LDS.128 + 16 FFMA.  Lane remap: warp tile 32i x 16d.
// ---------------------------------------------------------------------------
__global__ __launch_bounds__(256) void k_av()
{
    const int blk  = blockIdx.x;
    const int part = blk & 3;
    const int bh   = blk >> 2;
    const int b    = bh >> 3;
    const int h    = bh & 7;

    __shared__ float as_t[64 * 68];     // [j][i]
    __shared__ float vs  [64 * 68];     // [j][d]

    const int t  = threadIdx.x;
    const int w  = t >> 5, l = t & 31;
    const int ti = (w & 1) * 8 + (l >> 2);   // i-group
    const int td = (w >> 1) * 4 + (l & 3);   // d-group (4 consecutive d)

    #pragma unroll
    for (int k = 0; k < 16; k++) {
        int idx = t + k * 256;
        int i = idx >> 6, j = idx & 63;
        as_t[j * 68 + i] = g_attnw[(size_t)bh * 4096 + idx];
    }

    const float* vsrc = g_qkv2 + (size_t)b * C3 * HW + ((size_t)128 << 16);
    float* outb       = g_attout + (size_t)b * CIN * HW;

    for (int cc = 0; cc < 32; cc++) {
        const int chunk = part * 32 + cc;
        __syncthreads();
        #pragma unroll
        for (int k = 0; k < 16; k++) {
            int idx = t + k * 256;
            int tok = idx >> 6, d = idx & 63;
            vs[tok * 68 + d] = vsrc[qkv_off(idx, chunk, h)];
        }
        __syncthreads();

        float ao[4][4];
        #pragma unroll
        for (int i = 0; i < 4; i++)
            #pragma unroll
            for (int j = 0; j < 4; j++) ao[i][j] = 0.f;

        #pragma unroll 4
        for (int j = 0; j < 64; j++) {
            float4 a4 = *(const float4*)&as_t[j * 68 + ti * 4];
            float4 v4 = *(const float4*)&vs  [j * 68 + td * 4];
            ao[0][0] += a4.x * v4.x; ao[0][1] += a4.x * v4.y;
            ao[0][2] += a4.x * v4.z; ao[0][3] += a4.x * v4.w;
            ao[1][0] += a4.y * v4.x; ao[1][1] += a4.y * v4.y;
            ao[1][2] += a4.y * v4.z; ao[1][3] += a4.y * v4.w;
            ao[2][0] += a4.z * v4.x; ao[2][1] += a4.z * v4.y;
            ao[2][2] += a4.z * v4.z; ao[2][3] += a4.z * v4.w;
            ao[3][0] += a4.w * v4.x; ao[3][1] += a4.w * v4.y;
            ao[3][2] += a4.w * v4.z; ao[3][3] += a4.w * v4.w;
        }

        const int s   = td >> 3;
        const int b1  = (td * 4) & 31;
        const int seg = chunk * 2 + s;
        const int b0r = seg >> 6;
        const int c   = seg & 63;
        #pragma unroll
        for (int ii = 0; ii < 4; ii++) {
            int tok = ti * 4 + ii;
            int row = ((tok >> 3) << 5) + (h << 2) + b0r;
            int colp = ((tok & 7) << 5) + b1;
            float4 v4 = make_float4(ao[ii][0], ao[ii][1], ao[ii][2], ao[ii][3]);
            *(float4*)(outb + ((size_t)c << 16) + (size_t)(row << 8) + colp) = v4;
        }
    }
}

// ---------------------------------------------------------------------------
// K5: final 1x1 projection + bias -> d_out.
// ---------------------------------------------------------------------------
__global__ __launch_bounds__(256) void k_proj(const float* __restrict__ wm,
                                              const float* __restrict__ bias,
                                              float* __restrict__ out)
{
    const int b     = blockIdx.z;
    const int pBase = blockIdx.x * 256;

    __shared__ float Ws[64 * 64];
    __shared__ float Xs[16 * 256];
    __shared__ float Bs[64];

    const int t  = threadIdx.x;
    const int tx = t & 31;
    const int ty = t >> 5;

    #pragma unroll
    for (int i = 0; i < 16; i++)
        Ws[t + i * 256] = wm[t + i * 256];
    if (t < 64) Bs[t] = bias[t];

    float acc[8][8];
    #pragma unroll
    for (int i = 0; i < 8; i++)
        #pragma unroll
        for (int j = 0; j < 8; j++) acc[i][j] = 0.f;

    const float* xb = g_attout + (size_t)b * CIN * HW + pBase;

    for (int cb = 0; cb < 64; cb += 16) {
        __syncthreads();
        #pragma unroll
        for (int k = 0; k < 4; k++) {
            int idx = t + k * 256;
            int cc  = idx >> 6;
            int pp  = (idx & 63) << 2;
            float4 v = *(const float4*)(xb + (size_t)(cb + cc) * HW + pp);
            *(float4*)(&Xs[cc * 256 + pp]) = v;
        }
        __syncthreads();
        #pragma unroll
        for (int cc = 0; cc < 16; cc++) {
            float xr[8], wr[8];
            #pragma unroll
            for (int j = 0; j < 8; j++) xr[j] = Xs[cc * 256 + tx + j * 32];
            #pragma unroll
            for (int i = 0; i < 8; i++) wr[i] = Ws[(ty + i * 8) * 64 + cb + cc];
            #pragma unroll
            for (int i = 0; i < 8; i++)
                #pragma unroll
                for (int j = 0; j < 8; j++) acc[i][j] += wr[i] * xr[j];
        }
    }

    float* ob = out + (size_t)b * CIN * HW + pBase;
    #pragma unroll
    for (int i = 0; i < 8; i++) {
        float bb = Bs[ty + i * 8];
        #pragma unroll
        for (int j = 0; j < 8; j++)
            ob[(size_t)(ty + i * 8) * HW + tx + j * 32] = acc[i][j] + bb;
    }
}

// ---------------------------------------------------------------------------
extern "C" void kernel_launch(void* const* d_in, const int* in_sizes, int n_in,
                              void* d_out, int out_size)
{
    const float* x      = (const float*)d_in[0];
    const float* w_qkv  = (const float*)d_in[1];
    const float* w_dw   = (const float*)d_in[2];
    const float* w_proj = (const float*)d_in[3];
    const float* b_proj = (const float*)d_in[4];
    const float* pos    = (const float*)d_in[5];
    float* out = (float*)d_out;

    k_qkvdw<<<dim3(96, 8, BATCH), 256>>>(x, w_qkv, w_dw);
    k_simp <<<BATCH * HEADS * 4, 256>>>();
    k_soft <<<BATCH * HEADS, 256>>>(pos);
    k_av   <<<BATCH * HEADS * 4, 256>>>();
    k_proj <<<dim3(256, 1, BATCH), 256>>>(w_proj, b_proj, out);
}